// round 14
// baseline (speedup 1.0000x reference)
#include <cuda_runtime.h>
#include <cuda_bf16.h>

// Problem constants (fixed by the reference)
#define NN    20480      // B*P*A total nodes
#define AA    10         // agents per group
#define MID   128
#define TILE  32         // rows per block in encode/node kernels
#define ACT   8
#define RS    36         // transposed smem row stride (floats) for encode/node
#define ERS   52         // e1t row stride in k_edge

typedef unsigned long long ull;

// Scratch (device globals — no allocation allowed)
__device__ float g_n[NN * MID];
__device__ float g_u[NN * MID];
__device__ float g_v[NN * MID];     // includes b_e1 folded in
__device__ float g_agg[NN * MID];

// ---- packed f32x2 helpers ---------------------------------------------------
__device__ __forceinline__ ull pack2(float lo, float hi) {
    ull r; asm("mov.b64 %0, {%1, %2};" : "=l"(r) : "f"(lo), "f"(hi)); return r;
}
__device__ __forceinline__ void unpack2(ull v, float& lo, float& hi) {
    asm("mov.b64 {%0, %1}, %2;" : "=f"(lo), "=f"(hi) : "l"(v));
}
__device__ __forceinline__ void ffma2(ull& d, ull a, ull b) {
    asm("fma.rn.f32x2 %0, %1, %2, %0;" : "+l"(d) : "l"(a), "l"(b));
}
__device__ __forceinline__ ull lds64(const float* p) {
    return *reinterpret_cast<const ull*>(p);
}

// ---------------------------------------------------------------------------
// Generalized register-tiled GEMM fragment: 4 cols x NP row-pairs per thread.
//  acc[c][p] accumulates cols c0+c, rows (r0+2p, r0+2p+1).
//  Weights front-batched CHUNK at a time (CHUNK LDG.128 in flight).
// ---------------------------------------------------------------------------
template<int NP>
__device__ __forceinline__ void finit(ull (&acc)[4][NP], float4 b) {
    const float bc[4] = {b.x, b.y, b.z, b.w};
    #pragma unroll
    for (int c = 0; c < 4; c++) {
        const ull bb = pack2(bc[c], bc[c]);
        #pragma unroll
        for (int p = 0; p < NP; p++) acc[c][p] = bb;
    }
}

template<int NP, int CHUNK>
__device__ __forceinline__ void fgemm(ull (&acc)[4][NP],
                                      const float* __restrict__ in_t, int rs,
                                      const float* __restrict__ w,
                                      int K, int c0, int r0)
{
    for (int kk = 0; kk < K; kk += CHUNK) {
        float4 wv[CHUNK];
        #pragma unroll
        for (int t = 0; t < CHUNK; t++)
            wv[t] = *reinterpret_cast<const float4*>(w + (kk + t) * 128 + c0);
        #pragma unroll
        for (int t = 0; t < CHUNK; t++) {
            ull a[NP];
            #pragma unroll
            for (int p = 0; p < NP; p++)
                a[p] = lds64(in_t + (kk + t) * rs + r0 + 2 * p);
            const float wc[4] = {wv[t].x, wv[t].y, wv[t].z, wv[t].w};
            #pragma unroll
            for (int c = 0; c < 4; c++) {
                const ull b = pack2(wc[c], wc[c]);
                #pragma unroll
                for (int p = 0; p < NP; p++) ffma2(acc[c][p], a[p], b);
            }
        }
    }
}

template<int NP>
__device__ __forceinline__ void ffin(const ull (&acc)[4][NP], bool relu,
                                     float (&out)[4][2 * NP])
{
    #pragma unroll
    for (int c = 0; c < 4; c++)
        #pragma unroll
        for (int p = 0; p < NP; p++) {
            float lo, hi; unpack2(acc[c][p], lo, hi);
            if (relu) { lo = fmaxf(lo, 0.f); hi = fmaxf(hi, 0.f); }
            out[c][2 * p] = lo; out[c][2 * p + 1] = hi;
        }
}

// store [4 cols][2NP rows] into transposed smem [col][row] via STS.128
template<int NP>
__device__ __forceinline__ void store_t(float* buf, int rs, int c0, int r0,
                                        const float (&out)[4][2 * NP])
{
    #pragma unroll
    for (int c = 0; c < 4; c++)
        #pragma unroll
        for (int q = 0; q < NP / 2; q++)
            *reinterpret_cast<float4*>(buf + (c0 + c) * rs + r0 + 4 * q) =
                make_float4(out[c][4 * q], out[c][4 * q + 1],
                            out[c][4 * q + 2], out[c][4 * q + 3]);
}

// store to global [row][128] layout via STG.128 per row
template<int NP>
__device__ __forceinline__ void store_g(float* g, int row_base, int c0, int r0,
                                        const float (&out)[4][2 * NP])
{
    #pragma unroll
    for (int i = 0; i < 2 * NP; i++)
        *reinterpret_cast<float4*>(g + (row_base + r0 + i) * MID + c0) =
            make_float4(out[0][i], out[1][i], out[2][i], out[3][i]);
}

// ---------------------------------------------------------------------------
// KA: encoder (129 -> 128 relu -> 128) + u/v projections. 32 rows/block.
// lane -> cols 4*lane, warp -> rows 8*warp. smem 2 buffers (37KB).
// ---------------------------------------------------------------------------
__global__ __launch_bounds__(128)
void k_encode(const float* __restrict__ theta,
              const float* __restrict__ svec,
              const float* __restrict__ ivec,
              const float* __restrict__ w_in1, const float* __restrict__ b_in1,
              const float* __restrict__ w_in2, const float* __restrict__ b_in2,
              const float* __restrict__ w_e1,  const float* __restrict__ b_e1)
{
    __shared__ __align__(16) float bufA[129 * RS];   // xs, then n
    __shared__ __align__(16) float bufB[128 * RS];   // h

    const int j    = threadIdx.x;
    const int c0   = (j & 31) * 4;
    const int r0   = (j >> 5) * 8;
    const int base = blockIdx.x * TILE;

    for (int idx = j; idx < TILE * 129; idx += 128) {
        const int i = idx / 129, k = idx % 129;
        const int node = base + i;
        float val;
        if (k < 64)       val = theta[node * 64 + k];
        else if (k < 128) val = svec[node * 64 + (k - 64)];
        else              val = ivec[node];
        bufA[k * RS + i] = val;
    }
    __syncthreads();

    ull acc[4][4];
    float o[4][8];

    // in1: 129 -> 128, relu (K=128 in loop + manual tail k=128)
    finit<4>(acc, *reinterpret_cast<const float4*>(b_in1 + c0));
    fgemm<4, 4>(acc, bufA, RS, w_in1, 128, c0, r0);
    ffin<4>(acc, false, o);
    {
        const float4 wt = *reinterpret_cast<const float4*>(w_in1 + 128 * 128 + c0);
        const float wc[4] = {wt.x, wt.y, wt.z, wt.w};
        float a[8];
        #pragma unroll
        for (int i = 0; i < 8; i++) a[i] = bufA[128 * RS + r0 + i];
        #pragma unroll
        for (int c = 0; c < 4; c++)
            #pragma unroll
            for (int i = 0; i < 8; i++)
                o[c][i] = fmaxf(fmaf(a[i], wc[c], o[c][i]), 0.f);
    }
    store_t<4>(bufB, RS, c0, r0, o);
    __syncthreads();

    // in2: 128 -> 128 (no relu) -> n (bufA alias + global)
    finit<4>(acc, *reinterpret_cast<const float4*>(b_in2 + c0));
    fgemm<4, 4>(acc, bufB, RS, w_in2, 128, c0, r0);
    ffin<4>(acc, false, o);
    store_t<4>(bufA, RS, c0, r0, o);
    store_g<4>(g_n, base, c0, r0, o);
    __syncthreads();

    // u = n @ w_e1[0:128]
    finit<4>(acc, make_float4(0.f, 0.f, 0.f, 0.f));
    fgemm<4, 4>(acc, bufA, RS, w_e1, 128, c0, r0);
    ffin<4>(acc, false, o);
    store_g<4>(g_u, base, c0, r0, o);

    // v = n @ w_e1[128:256] + b_e1
    finit<4>(acc, *reinterpret_cast<const float4*>(b_e1 + c0));
    fgemm<4, 4>(acc, bufA, RS, w_e1 + 128 * 128, 128, c0, r0);
    ffin<4>(acc, false, o);
    store_g<4>(g_v, base, c0, r0, o);
}

// ---------------------------------------------------------------------------
// KB: one block per group (2048 blocks). e1 (45 rows, pad 48) transposed,
// e2 in ONE k-pass per half (NP=6: warp owns 12 rows), in-place overwrite,
// relu-sum per receiver (e3 linearity), e3 on 10 summed rows. Zero atomics.
// ---------------------------------------------------------------------------
__global__ __launch_bounds__(128)
void k_edge(const float* __restrict__ w_e2, const float* __restrict__ b_e2,
            const float* __restrict__ w_e3, const float* __restrict__ b_e3)
{
    __shared__ __align__(16) float u_s[10 * 128];
    __shared__ __align__(16) float v_s[10 * 128];
    __shared__ __align__(16) float e1t[128 * ERS];
    __shared__ __align__(16) float s2t[128 * 16];

    const int j     = threadIdx.x;
    const int c0    = (j & 31) * 4;
    const int r12   = (j >> 5) * 12;   // e2 row base (12 rows per warp)
    const int r4    = (j >> 5) * 4;    // e3 row base
    const int gbase = blockIdx.x * AA;

    #pragma unroll
    for (int a = 0; a < 10; a++) {
        u_s[a * 128 + j] = g_u[(gbase + a) * MID + j];
        v_s[a * 128 + j] = g_v[(gbase + a) * MID + j];
    }
    __syncthreads();

    const float4 be2 = *reinterpret_cast<const float4*>(b_e2 + c0);

    for (int half = 0; half < 2; half++) {
        // build e1 rows: row = r_loc*9 + ss, receiver r = half*5 + r_loc
        {
            float v[5];
            #pragma unroll
            for (int rl = 0; rl < 5; rl++) v[rl] = v_s[(half * 5 + rl) * 128 + j];
            #pragma unroll
            for (int m = 0; m < 12; m++) {
                float q[4];
                #pragma unroll
                for (int t = 0; t < 4; t++) {
                    const int row = 4 * m + t;
                    if (row < 45) {
                        const int rl = row / 9, ss = row % 9;
                        const int r  = half * 5 + rl;
                        const int s  = (ss < r) ? ss : ss + 1;
                        q[t] = fmaxf(u_s[s * 128 + j] + v[rl], 0.f);
                    } else q[t] = 0.f;
                }
                *reinterpret_cast<float4*>(e1t + j * ERS + 4 * m) =
                    make_float4(q[0], q[1], q[2], q[3]);
            }
        }
        __syncthreads();

        // e2: all 48 rows in ONE weight pass, relu, in-place (warp-disjoint)
        {
            ull acc6[4][6];
            finit<6>(acc6, be2);
            fgemm<6, 4>(acc6, e1t, ERS, w_e2, 128, c0, r12);
            float o12[4][12];
            ffin<6>(acc6, true, o12);
            store_t<6>(e1t, ERS, c0, r12, o12);
        }
        __syncthreads();

        // relu-sum over 9 senders per receiver -> s2t[k][recv]
        {
            const float* myrow = e1t + j * ERS;
            #pragma unroll
            for (int rl = 0; rl < 5; rl++) {
                float s = 0.f;
                #pragma unroll
                for (int ss = 0; ss < 9; ss++) s += myrow[rl * 9 + ss];
                s2t[j * 16 + half * 5 + rl] = s;
            }
            if (half == 0) {
                #pragma unroll
                for (int r = 10; r < 16; r++) s2t[j * 16 + r] = 0.f;
            }
        }
        __syncthreads();
    }

    // e3: 10 rows x 128 cols; agg = acc/9 + b_e3
    if (r4 < 10) {
        ull acc2[4][2];
        finit<2>(acc2, make_float4(0.f, 0.f, 0.f, 0.f));
        fgemm<2, 4>(acc2, s2t, 16, w_e3, 128, c0, r4);
        float o[4][4];
        ffin<2>(acc2, false, o);
        const float4 be3 = *reinterpret_cast<const float4*>(b_e3 + c0);
        const float bs[4] = {be3.x, be3.y, be3.z, be3.w};
        #pragma unroll
        for (int i = 0; i < 4; i++) {
            if (r4 + i < 10)
                *reinterpret_cast<float4*>(g_agg + (gbase + r4 + i) * MID + c0) =
                    make_float4(o[0][i] * (1.f / 9.f) + bs[0],
                                o[1][i] * (1.f / 9.f) + bs[1],
                                o[2][i] * (1.f / 9.f) + bs[2],
                                o[3][i] * (1.f / 9.f) + bs[3]);
        }
    }
}

// ---------------------------------------------------------------------------
// KC: node MLP (256 -> 128 relu -> 128 relu -> 128) + decoder (128 relu -> 8)
// 32 rows/block. n1's 256-wide input = two K=128 passes sharing one acc
// (g_n pass, then g_agg overwrites the same buffer). Two smem buffers.
// ---------------------------------------------------------------------------
__global__ __launch_bounds__(128)
void k_node(const float* __restrict__ w_n1, const float* __restrict__ b_n1,
            const float* __restrict__ w_n2, const float* __restrict__ b_n2,
            const float* __restrict__ w_n3, const float* __restrict__ b_n3,
            const float* __restrict__ w_l1, const float* __restrict__ b_l1,
            const float* __restrict__ w_l2, const float* __restrict__ b_l2,
            float* __restrict__ out)
{
    __shared__ __align__(16) float bufA[128 * RS];
    __shared__ __align__(16) float bufB[128 * RS];

    const int j    = threadIdx.x;
    const int c0   = (j & 31) * 4;
    const int r0   = (j >> 5) * 8;
    const int base = blockIdx.x * TILE;

    // load g_n part
    for (int idx = j; idx < TILE * 128; idx += 128) {
        const int i = idx >> 7, k = idx & 127;
        bufA[k * RS + i] = g_n[(base + i) * MID + k];
    }
    __syncthreads();

    ull acc[4][4];
    float o[4][8];

    // n1 part 1: over g_n with w_n1[0:128]
    finit<4>(acc, *reinterpret_cast<const float4*>(b_n1 + c0));
    fgemm<4, 4>(acc, bufA, RS, w_n1, 128, c0, r0);
    __syncthreads();                       // all reads of bufA done

    // swap in g_agg, accumulate with w_n1[128:256]
    for (int idx = j; idx < TILE * 128; idx += 128) {
        const int i = idx >> 7, k = idx & 127;
        bufA[k * RS + i] = g_agg[(base + i) * MID + k];
    }
    __syncthreads();
    fgemm<4, 4>(acc, bufA, RS, w_n1 + 128 * 128, 128, c0, r0);
    ffin<4>(acc, true, o);
    store_t<4>(bufB, RS, c0, r0, o);
    __syncthreads();

    // n2: bufB -> bufA, relu
    finit<4>(acc, *reinterpret_cast<const float4*>(b_n2 + c0));
    fgemm<4, 4>(acc, bufB, RS, w_n2, 128, c0, r0);
    ffin<4>(acc, true, o);
    store_t<4>(bufA, RS, c0, r0, o);
    __syncthreads();

    // n3: bufA -> bufB, no relu
    finit<4>(acc, *reinterpret_cast<const float4*>(b_n3 + c0));
    fgemm<4, 4>(acc, bufA, RS, w_n3, 128, c0, r0);
    ffin<4>(acc, false, o);
    store_t<4>(bufB, RS, c0, r0, o);
    __syncthreads();

    // l1: bufB -> bufA, relu
    finit<4>(acc, *reinterpret_cast<const float4*>(b_l1 + c0));
    fgemm<4, 4>(acc, bufB, RS, w_l1, 128, c0, r0);
    ffin<4>(acc, true, o);
    store_t<4>(bufA, RS, c0, r0, o);
    __syncthreads();

    // l2: 128 -> 8. 256 outputs, 128 threads -> 2 each
    {
        const int c = j & 7;
        #pragma unroll
        for (int rr = 0; rr < 2; rr++) {
            const int i = (j >> 3) + rr * 16;
            float s = b_l2[c];
            #pragma unroll 8
            for (int k = 0; k < 128; k++)
                s = fmaf(bufA[k * RS + i], w_l2[k * ACT + c], s);
            out[(base + i) * ACT + c] = s;
        }
    }
}

// ---------------------------------------------------------------------------
// Host-side input resolution by SIZE CLASS (== dict mapping, proven R7).
// ---------------------------------------------------------------------------
extern "C" void kernel_launch(void* const* d_in, const int* in_sizes, int n_in,
                              void* d_out, int out_size)
{
    int scale = 1;
    {
        bool elems = false, bytes = false;
        for (int t = 0; t < n_in; t++) {
            if (in_sizes[t] == 16512) elems = true;
            if (in_sizes[t] == 66048) bytes = true;
        }
        if (!elems && bytes) scale = 4;
    }

    int posBig[2] = {-1, -1}; int nBig = 0;
    int posW32[2] = {-1, -1}; int nW32 = 0;
    int posW16[6] = {-1, -1, -1, -1, -1, -1}; int nW16 = 0;
    int posB[9]   = {-1, -1, -1, -1, -1, -1, -1, -1, -1}; int nB = 0;
    int pI = -1, pWin1 = -1, pWl2 = -1, pBl2 = -1;

    for (int t = 0; t < n_in; t++) {
        const int sz = in_sizes[t] / scale;
        if      (sz == 1310720) { if (nBig < 2) posBig[nBig++] = t; }
        else if (sz == 32768)   { if (nW32 < 2) posW32[nW32++] = t; }
        else if (sz == 16384)   { if (nW16 < 6) posW16[nW16++] = t; }
        else if (sz == 128)     { if (nB   < 9) posB[nB++]     = t; }
        else if (sz == 20480)   { pI    = t; }
        else if (sz == 16512)   { pWin1 = t; }
        else if (sz == 1024)    { pWl2  = t; }
        else if (sz == 8)       { pBl2  = t; }
    }

    if (nBig < 2 || nW32 < 2 || nW16 < 6 || nB < 9 ||
        pI < 0 || pWin1 < 0 || pWl2 < 0 || pBl2 < 0) {
        posBig[0] = 0;  posBig[1] = 1;  pI = 2;
        pWin1 = 5;
        posB[0] = 6;    posW16[0] = 7;  posB[1] = 8;
        posW32[0] = 9;  posB[2] = 10;
        posW16[1] = 11; posB[3] = 12;
        posW16[2] = 13; posB[4] = 14;
        posW32[1] = 15; posB[5] = 16;
        posW16[3] = 17; posB[6] = 18;
        posW16[4] = 19; posB[7] = 20;
        posW16[5] = 21; posB[8] = 22;
        pWl2 = 23; pBl2 = 24;
    }

    const float* theta = (const float*)d_in[posBig[0]];
    const float* svec  = (const float*)d_in[posBig[1]];
    const float* ivec  = (const float*)d_in[pI];
    const float* w_in1 = (const float*)d_in[pWin1];
    const float* w_in2 = (const float*)d_in[posW16[0]];
    const float* w_e1  = (const float*)d_in[posW32[0]];
    const float* w_e2  = (const float*)d_in[posW16[1]];
    const float* w_e3  = (const float*)d_in[posW16[2]];
    const float* w_n1  = (const float*)d_in[posW32[1]];
    const float* w_n2  = (const float*)d_in[posW16[3]];
    const float* w_n3  = (const float*)d_in[posW16[4]];
    const float* w_l1  = (const float*)d_in[posW16[5]];
    const float* w_l2  = (const float*)d_in[pWl2];
    const float* b_in1 = (const float*)d_in[posB[0]];
    const float* b_in2 = (const float*)d_in[posB[1]];
    const float* b_e1  = (const float*)d_in[posB[2]];
    const float* b_e2  = (const float*)d_in[posB[3]];
    const float* b_e3  = (const float*)d_in[posB[4]];
    const float* b_n1  = (const float*)d_in[posB[5]];
    const float* b_n2  = (const float*)d_in[posB[6]];
    const float* b_n3  = (const float*)d_in[posB[7]];
    const float* b_l1  = (const float*)d_in[posB[8]];
    const float* b_l2  = (const float*)d_in[pBl2];
    float* out = (float*)d_out;

    k_encode<<<NN / TILE, 128>>>(theta, svec, ivec,
                                 w_in1, b_in1, w_in2, b_in2, w_e1, b_e1);
    k_edge<<<NN / AA, 128>>>(w_e2, b_e2, w_e3, b_e3);
    k_node<<<NN / TILE, 128>>>(w_n1, b_n1, w_n2, b_n2, w_n3, b_n3,
                               w_l1, b_l1, w_l2, b_l2, out);
}

// round 15
// speedup vs baseline: 1.0012x; 1.0012x over previous
#include <cuda_runtime.h>
#include <cuda_bf16.h>

// Problem constants (fixed by the reference)
#define NN    20480      // B*P*A total nodes
#define AA    10         // agents per group
#define MID   128
#define TILE  32         // rows per block in encode/node kernels
#define ACT   8
#define RS    36         // transposed smem row stride (floats) for encode/node
#define ERS   52         // e1t row stride in k_edge

typedef unsigned long long ull;

// Scratch (device globals — no allocation allowed)
__device__ float g_n[NN * MID];
__device__ float g_u[NN * MID];
__device__ float g_v[NN * MID];     // includes b_e1 folded in
__device__ float g_agg[NN * MID];

// ---- packed f32x2 helpers ---------------------------------------------------
__device__ __forceinline__ ull pack2(float lo, float hi) {
    ull r; asm("mov.b64 %0, {%1, %2};" : "=l"(r) : "f"(lo), "f"(hi)); return r;
}
__device__ __forceinline__ void unpack2(ull v, float& lo, float& hi) {
    asm("mov.b64 {%0, %1}, %2;" : "=f"(lo), "=f"(hi) : "l"(v));
}
__device__ __forceinline__ void ffma2(ull& d, ull a, ull b) {
    asm("fma.rn.f32x2 %0, %1, %2, %0;" : "+l"(d) : "l"(a), "l"(b));
}
__device__ __forceinline__ ull lds64(const float* p) {
    return *reinterpret_cast<const ull*>(p);
}

// ---------------------------------------------------------------------------
// Generalized register-tiled GEMM fragment: 4 cols x NP row-pairs per thread.
//  acc[c][p] accumulates cols c0+c, rows (r0+2p, r0+2p+1).
//  Weights front-batched CHUNK at a time (CHUNK LDG.128 in flight).
// ---------------------------------------------------------------------------
template<int NP>
__device__ __forceinline__ void finit(ull (&acc)[4][NP], float4 b) {
    const float bc[4] = {b.x, b.y, b.z, b.w};
    #pragma unroll
    for (int c = 0; c < 4; c++) {
        const ull bb = pack2(bc[c], bc[c]);
        #pragma unroll
        for (int p = 0; p < NP; p++) acc[c][p] = bb;
    }
}

template<int NP, int CHUNK>
__device__ __forceinline__ void fgemm(ull (&acc)[4][NP],
                                      const float* __restrict__ in_t, int rs,
                                      const float* __restrict__ w,
                                      int K, int c0, int r0)
{
    for (int kk = 0; kk < K; kk += CHUNK) {
        float4 wv[CHUNK];
        #pragma unroll
        for (int t = 0; t < CHUNK; t++)
            wv[t] = *reinterpret_cast<const float4*>(w + (kk + t) * 128 + c0);
        #pragma unroll
        for (int t = 0; t < CHUNK; t++) {
            ull a[NP];
            #pragma unroll
            for (int p = 0; p < NP; p++)
                a[p] = lds64(in_t + (kk + t) * rs + r0 + 2 * p);
            const float wc[4] = {wv[t].x, wv[t].y, wv[t].z, wv[t].w};
            #pragma unroll
            for (int c = 0; c < 4; c++) {
                const ull b = pack2(wc[c], wc[c]);
                #pragma unroll
                for (int p = 0; p < NP; p++) ffma2(acc[c][p], a[p], b);
            }
        }
    }
}

template<int NP>
__device__ __forceinline__ void ffin(const ull (&acc)[4][NP], bool relu,
                                     float (&out)[4][2 * NP])
{
    #pragma unroll
    for (int c = 0; c < 4; c++)
        #pragma unroll
        for (int p = 0; p < NP; p++) {
            float lo, hi; unpack2(acc[c][p], lo, hi);
            if (relu) { lo = fmaxf(lo, 0.f); hi = fmaxf(hi, 0.f); }
            out[c][2 * p] = lo; out[c][2 * p + 1] = hi;
        }
}

// store [4 cols][2NP rows] into transposed smem [col][row] via STS.128
template<int NP>
__device__ __forceinline__ void store_t(float* buf, int rs, int c0, int r0,
                                        const float (&out)[4][2 * NP])
{
    #pragma unroll
    for (int c = 0; c < 4; c++)
        #pragma unroll
        for (int q = 0; q < NP / 2; q++)
            *reinterpret_cast<float4*>(buf + (c0 + c) * rs + r0 + 4 * q) =
                make_float4(out[c][4 * q], out[c][4 * q + 1],
                            out[c][4 * q + 2], out[c][4 * q + 3]);
}

// store to global [row][128] layout via STG.128 per row
template<int NP>
__device__ __forceinline__ void store_g(float* g, int row_base, int c0, int r0,
                                        const float (&out)[4][2 * NP])
{
    #pragma unroll
    for (int i = 0; i < 2 * NP; i++)
        *reinterpret_cast<float4*>(g + (row_base + r0 + i) * MID + c0) =
            make_float4(out[0][i], out[1][i], out[2][i], out[3][i]);
}

// ---------------------------------------------------------------------------
// KA: encoder (129 -> 128 relu -> 128) + u/v projections. 32 rows/block.
// lane -> cols 4*lane, warp -> rows 8*warp. smem 2 buffers (37KB).
// ---------------------------------------------------------------------------
__global__ __launch_bounds__(128)
void k_encode(const float* __restrict__ theta,
              const float* __restrict__ svec,
              const float* __restrict__ ivec,
              const float* __restrict__ w_in1, const float* __restrict__ b_in1,
              const float* __restrict__ w_in2, const float* __restrict__ b_in2,
              const float* __restrict__ w_e1,  const float* __restrict__ b_e1)
{
    __shared__ __align__(16) float bufA[129 * RS];   // xs, then n
    __shared__ __align__(16) float bufB[128 * RS];   // h

    const int j    = threadIdx.x;
    const int c0   = (j & 31) * 4;
    const int r0   = (j >> 5) * 8;
    const int base = blockIdx.x * TILE;

    for (int idx = j; idx < TILE * 129; idx += 128) {
        const int i = idx / 129, k = idx % 129;
        const int node = base + i;
        float val;
        if (k < 64)       val = theta[node * 64 + k];
        else if (k < 128) val = svec[node * 64 + (k - 64)];
        else              val = ivec[node];
        bufA[k * RS + i] = val;
    }
    __syncthreads();

    ull acc[4][4];
    float o[4][8];

    // in1: 129 -> 128, relu (K=128 in loop + manual tail k=128)
    finit<4>(acc, *reinterpret_cast<const float4*>(b_in1 + c0));
    fgemm<4, 4>(acc, bufA, RS, w_in1, 128, c0, r0);
    ffin<4>(acc, false, o);
    {
        const float4 wt = *reinterpret_cast<const float4*>(w_in1 + 128 * 128 + c0);
        const float wc[4] = {wt.x, wt.y, wt.z, wt.w};
        float a[8];
        #pragma unroll
        for (int i = 0; i < 8; i++) a[i] = bufA[128 * RS + r0 + i];
        #pragma unroll
        for (int c = 0; c < 4; c++)
            #pragma unroll
            for (int i = 0; i < 8; i++)
                o[c][i] = fmaxf(fmaf(a[i], wc[c], o[c][i]), 0.f);
    }
    store_t<4>(bufB, RS, c0, r0, o);
    __syncthreads();

    // in2: 128 -> 128 (no relu) -> n (bufA alias + global)
    finit<4>(acc, *reinterpret_cast<const float4*>(b_in2 + c0));
    fgemm<4, 4>(acc, bufB, RS, w_in2, 128, c0, r0);
    ffin<4>(acc, false, o);
    store_t<4>(bufA, RS, c0, r0, o);
    store_g<4>(g_n, base, c0, r0, o);
    __syncthreads();

    // u = n @ w_e1[0:128]
    finit<4>(acc, make_float4(0.f, 0.f, 0.f, 0.f));
    fgemm<4, 4>(acc, bufA, RS, w_e1, 128, c0, r0);
    ffin<4>(acc, false, o);
    store_g<4>(g_u, base, c0, r0, o);

    // v = n @ w_e1[128:256] + b_e1
    finit<4>(acc, *reinterpret_cast<const float4*>(b_e1 + c0));
    fgemm<4, 4>(acc, bufA, RS, w_e1 + 128 * 128, 128, c0, r0);
    ffin<4>(acc, false, o);
    store_g<4>(g_v, base, c0, r0, o);
}

// ---------------------------------------------------------------------------
// KB: one block per group (2048 blocks). e1 (45 rows, pad 48) transposed,
// e2 in ONE k-pass per half (NP=6: warp owns 12 rows), in-place overwrite,
// relu-sum per receiver (e3 linearity), e3 on 10 summed rows. Zero atomics.
// ---------------------------------------------------------------------------
__global__ __launch_bounds__(128)
void k_edge(const float* __restrict__ w_e2, const float* __restrict__ b_e2,
            const float* __restrict__ w_e3, const float* __restrict__ b_e3)
{
    __shared__ __align__(16) float u_s[10 * 128];
    __shared__ __align__(16) float v_s[10 * 128];
    __shared__ __align__(16) float e1t[128 * ERS];
    __shared__ __align__(16) float s2t[128 * 16];

    const int j     = threadIdx.x;
    const int c0    = (j & 31) * 4;
    const int r12   = (j >> 5) * 12;   // e2 row base (12 rows per warp)
    const int r4    = (j >> 5) * 4;    // e3 row base
    const int gbase = blockIdx.x * AA;

    #pragma unroll
    for (int a = 0; a < 10; a++) {
        u_s[a * 128 + j] = g_u[(gbase + a) * MID + j];
        v_s[a * 128 + j] = g_v[(gbase + a) * MID + j];
    }
    __syncthreads();

    const float4 be2 = *reinterpret_cast<const float4*>(b_e2 + c0);

    for (int half = 0; half < 2; half++) {
        // build e1 rows: row = r_loc*9 + ss, receiver r = half*5 + r_loc
        {
            float v[5];
            #pragma unroll
            for (int rl = 0; rl < 5; rl++) v[rl] = v_s[(half * 5 + rl) * 128 + j];
            #pragma unroll
            for (int m = 0; m < 12; m++) {
                float q[4];
                #pragma unroll
                for (int t = 0; t < 4; t++) {
                    const int row = 4 * m + t;
                    if (row < 45) {
                        const int rl = row / 9, ss = row % 9;
                        const int r  = half * 5 + rl;
                        const int s  = (ss < r) ? ss : ss + 1;
                        q[t] = fmaxf(u_s[s * 128 + j] + v[rl], 0.f);
                    } else q[t] = 0.f;
                }
                *reinterpret_cast<float4*>(e1t + j * ERS + 4 * m) =
                    make_float4(q[0], q[1], q[2], q[3]);
            }
        }
        __syncthreads();

        // e2: all 48 rows in ONE weight pass, relu, in-place (warp-disjoint)
        {
            ull acc6[4][6];
            finit<6>(acc6, be2);
            fgemm<6, 4>(acc6, e1t, ERS, w_e2, 128, c0, r12);
            float o12[4][12];
            ffin<6>(acc6, true, o12);
            store_t<6>(e1t, ERS, c0, r12, o12);
        }
        __syncthreads();

        // relu-sum over 9 senders per receiver -> s2t[k][recv]
        {
            const float* myrow = e1t + j * ERS;
            #pragma unroll
            for (int rl = 0; rl < 5; rl++) {
                float s = 0.f;
                #pragma unroll
                for (int ss = 0; ss < 9; ss++) s += myrow[rl * 9 + ss];
                s2t[j * 16 + half * 5 + rl] = s;
            }
            if (half == 0) {
                #pragma unroll
                for (int r = 10; r < 16; r++) s2t[j * 16 + r] = 0.f;
            }
        }
        __syncthreads();
    }

    // e3: 10 rows x 128 cols; agg = acc/9 + b_e3
    if (r4 < 10) {
        ull acc2[4][2];
        finit<2>(acc2, make_float4(0.f, 0.f, 0.f, 0.f));
        fgemm<2, 4>(acc2, s2t, 16, w_e3, 128, c0, r4);
        float o[4][4];
        ffin<2>(acc2, false, o);
        const float4 be3 = *reinterpret_cast<const float4*>(b_e3 + c0);
        const float bs[4] = {be3.x, be3.y, be3.z, be3.w};
        #pragma unroll
        for (int i = 0; i < 4; i++) {
            if (r4 + i < 10)
                *reinterpret_cast<float4*>(g_agg + (gbase + r4 + i) * MID + c0) =
                    make_float4(o[0][i] * (1.f / 9.f) + bs[0],
                                o[1][i] * (1.f / 9.f) + bs[1],
                                o[2][i] * (1.f / 9.f) + bs[2],
                                o[3][i] * (1.f / 9.f) + bs[3]);
        }
    }
}

// ---------------------------------------------------------------------------
// KC: node MLP (256 -> 128 relu -> 128 relu -> 128) + decoder (128 relu -> 8)
// 32 rows/block. n1's 256-wide input = two K=128 passes sharing one acc
// (g_n pass, then g_agg overwrites the same buffer). Two smem buffers.
// ---------------------------------------------------------------------------
__global__ __launch_bounds__(128)
void k_node(const float* __restrict__ w_n1, const float* __restrict__ b_n1,
            const float* __restrict__ w_n2, const float* __restrict__ b_n2,
            const float* __restrict__ w_n3, const float* __restrict__ b_n3,
            const float* __restrict__ w_l1, const float* __restrict__ b_l1,
            const float* __restrict__ w_l2, const float* __restrict__ b_l2,
            float* __restrict__ out)
{
    __shared__ __align__(16) float bufA[128 * RS];
    __shared__ __align__(16) float bufB[128 * RS];

    const int j    = threadIdx.x;
    const int c0   = (j & 31) * 4;
    const int r0   = (j >> 5) * 8;
    const int base = blockIdx.x * TILE;

    // load g_n part
    for (int idx = j; idx < TILE * 128; idx += 128) {
        const int i = idx >> 7, k = idx & 127;
        bufA[k * RS + i] = g_n[(base + i) * MID + k];
    }
    __syncthreads();

    ull acc[4][4];
    float o[4][8];

    // n1 part 1: over g_n with w_n1[0:128]
    finit<4>(acc, *reinterpret_cast<const float4*>(b_n1 + c0));
    fgemm<4, 4>(acc, bufA, RS, w_n1, 128, c0, r0);
    __syncthreads();                       // all reads of bufA done

    // swap in g_agg, accumulate with w_n1[128:256]
    for (int idx = j; idx < TILE * 128; idx += 128) {
        const int i = idx >> 7, k = idx & 127;
        bufA[k * RS + i] = g_agg[(base + i) * MID + k];
    }
    __syncthreads();
    fgemm<4, 4>(acc, bufA, RS, w_n1 + 128 * 128, 128, c0, r0);
    ffin<4>(acc, true, o);
    store_t<4>(bufB, RS, c0, r0, o);
    __syncthreads();

    // n2: bufB -> bufA, relu
    finit<4>(acc, *reinterpret_cast<const float4*>(b_n2 + c0));
    fgemm<4, 4>(acc, bufB, RS, w_n2, 128, c0, r0);
    ffin<4>(acc, true, o);
    store_t<4>(bufA, RS, c0, r0, o);
    __syncthreads();

    // n3: bufA -> bufB, no relu
    finit<4>(acc, *reinterpret_cast<const float4*>(b_n3 + c0));
    fgemm<4, 4>(acc, bufA, RS, w_n3, 128, c0, r0);
    ffin<4>(acc, false, o);
    store_t<4>(bufB, RS, c0, r0, o);
    __syncthreads();

    // l1: bufB -> bufA, relu
    finit<4>(acc, *reinterpret_cast<const float4*>(b_l1 + c0));
    fgemm<4, 4>(acc, bufB, RS, w_l1, 128, c0, r0);
    ffin<4>(acc, true, o);
    store_t<4>(bufA, RS, c0, r0, o);
    __syncthreads();

    // l2: 128 -> 8. 256 outputs, 128 threads -> 2 each
    {
        const int c = j & 7;
        #pragma unroll
        for (int rr = 0; rr < 2; rr++) {
            const int i = (j >> 3) + rr * 16;
            float s = b_l2[c];
            #pragma unroll 8
            for (int k = 0; k < 128; k++)
                s = fmaf(bufA[k * RS + i], w_l2[k * ACT + c], s);
            out[(base + i) * ACT + c] = s;
        }
    }
}

// ---------------------------------------------------------------------------
// Host-side input resolution by SIZE CLASS (== dict mapping, proven R7).
// ---------------------------------------------------------------------------
extern "C" void kernel_launch(void* const* d_in, const int* in_sizes, int n_in,
                              void* d_out, int out_size)
{
    int scale = 1;
    {
        bool elems = false, bytes = false;
        for (int t = 0; t < n_in; t++) {
            if (in_sizes[t] == 16512) elems = true;
            if (in_sizes[t] == 66048) bytes = true;
        }
        if (!elems && bytes) scale = 4;
    }

    int posBig[2] = {-1, -1}; int nBig = 0;
    int posW32[2] = {-1, -1}; int nW32 = 0;
    int posW16[6] = {-1, -1, -1, -1, -1, -1}; int nW16 = 0;
    int posB[9]   = {-1, -1, -1, -1, -1, -1, -1, -1, -1}; int nB = 0;
    int pI = -1, pWin1 = -1, pWl2 = -1, pBl2 = -1;

    for (int t = 0; t < n_in; t++) {
        const int sz = in_sizes[t] / scale;
        if      (sz == 1310720) { if (nBig < 2) posBig[nBig++] = t; }
        else if (sz == 32768)   { if (nW32 < 2) posW32[nW32++] = t; }
        else if (sz == 16384)   { if (nW16 < 6) posW16[nW16++] = t; }
        else if (sz == 128)     { if (nB   < 9) posB[nB++]     = t; }
        else if (sz == 20480)   { pI    = t; }
        else if (sz == 16512)   { pWin1 = t; }
        else if (sz == 1024)    { pWl2  = t; }
        else if (sz == 8)       { pBl2  = t; }
    }

    if (nBig < 2 || nW32 < 2 || nW16 < 6 || nB < 9 ||
        pI < 0 || pWin1 < 0 || pWl2 < 0 || pBl2 < 0) {
        posBig[0] = 0;  posBig[1] = 1;  pI = 2;
        pWin1 = 5;
        posB[0] = 6;    posW16[0] = 7;  posB[1] = 8;
        posW32[0] = 9;  posB[2] = 10;
        posW16[1] = 11; posB[3] = 12;
        posW16[2] = 13; posB[4] = 14;
        posW32[1] = 15; posB[5] = 16;
        posW16[3] = 17; posB[6] = 18;
        posW16[4] = 19; posB[7] = 20;
        posW16[5] = 21; posB[8] = 22;
        pWl2 = 23; pBl2 = 24;
    }

    const float* theta = (const float*)d_in[posBig[0]];
    const float* svec  = (const float*)d_in[posBig[1]];
    const float* ivec  = (const float*)d_in[pI];
    const float* w_in1 = (const float*)d_in[pWin1];
    const float* w_in2 = (const float*)d_in[posW16[0]];
    const float* w_e1  = (const float*)d_in[posW32[0]];
    const float* w_e2  = (const float*)d_in[posW16[1]];
    const float* w_e3  = (const float*)d_in[posW16[2]];
    const float* w_n1  = (const float*)d_in[posW32[1]];
    const float* w_n2  = (const float*)d_in[posW16[3]];
    const float* w_n3  = (const float*)d_in[posW16[4]];
    const float* w_l1  = (const float*)d_in[posW16[5]];
    const float* w_l2  = (const float*)d_in[pWl2];
    const float* b_in1 = (const float*)d_in[posB[0]];
    const float* b_in2 = (const float*)d_in[posB[1]];
    const float* b_e1  = (const float*)d_in[posB[2]];
    const float* b_e2  = (const float*)d_in[posB[3]];
    const float* b_e3  = (const float*)d_in[posB[4]];
    const float* b_n1  = (const float*)d_in[posB[5]];
    const float* b_n2  = (const float*)d_in[posB[6]];
    const float* b_n3  = (const float*)d_in[posB[7]];
    const float* b_l1  = (const float*)d_in[posB[8]];
    const float* b_l2  = (const float*)d_in[pBl2];
    float* out = (float*)d_out;

    k_encode<<<NN / TILE, 128>>>(theta, svec, ivec,
                                 w_in1, b_in1, w_in2, b_in2, w_e1, b_e1);
    k_edge<<<NN / AA, 128>>>(w_e2, b_e2, w_e3, b_e3);
    k_node<<<NN / TILE, 128>>>(w_n1, b_n1, w_n2, b_n2, w_n3, b_n3,
                               w_l1, b_l1, w_l2, b_l2, out);
}

// round 16
// speedup vs baseline: 1.0016x; 1.0004x over previous
#include <cuda_runtime.h>
#include <cuda_bf16.h>

// Problem constants (fixed by the reference)
#define NN    20480      // B*P*A total nodes
#define AA    10         // agents per group
#define MID   128
#define TILE  32         // rows per block in encode/node kernels
#define ACT   8
#define RS    36         // transposed smem row stride (floats) for encode/node
#define ERS   52         // e1t row stride in k_edge

typedef unsigned long long ull;

// Scratch (device globals — no allocation allowed)
__device__ float g_n[NN * MID];
__device__ float g_u[NN * MID];
__device__ float g_v[NN * MID];     // includes b_e1 folded in
__device__ float g_agg[NN * MID];

// ---- packed f32x2 helpers ---------------------------------------------------
__device__ __forceinline__ ull pack2(float lo, float hi) {
    ull r; asm("mov.b64 %0, {%1, %2};" : "=l"(r) : "f"(lo), "f"(hi)); return r;
}
__device__ __forceinline__ void unpack2(ull v, float& lo, float& hi) {
    asm("mov.b64 {%0, %1}, %2;" : "=f"(lo), "=f"(hi) : "l"(v));
}
__device__ __forceinline__ void ffma2(ull& d, ull a, ull b) {
    asm("fma.rn.f32x2 %0, %1, %2, %0;" : "+l"(d) : "l"(a), "l"(b));
}
__device__ __forceinline__ ull lds64(const float* p) {
    return *reinterpret_cast<const ull*>(p);
}

// ---------------------------------------------------------------------------
// Generalized register-tiled GEMM fragment: 4 cols x NP row-pairs per thread.
//  acc[c][p] accumulates cols c0+c, rows (r0+2p, r0+2p+1).
//  Weights front-batched CHUNK at a time (CHUNK LDG.128 in flight).
// ---------------------------------------------------------------------------
template<int NP>
__device__ __forceinline__ void finit(ull (&acc)[4][NP], float4 b) {
    const float bc[4] = {b.x, b.y, b.z, b.w};
    #pragma unroll
    for (int c = 0; c < 4; c++) {
        const ull bb = pack2(bc[c], bc[c]);
        #pragma unroll
        for (int p = 0; p < NP; p++) acc[c][p] = bb;
    }
}

template<int NP, int CHUNK>
__device__ __forceinline__ void fgemm(ull (&acc)[4][NP],
                                      const float* __restrict__ in_t, int rs,
                                      const float* __restrict__ w,
                                      int K, int c0, int r0)
{
    for (int kk = 0; kk < K; kk += CHUNK) {
        float4 wv[CHUNK];
        #pragma unroll
        for (int t = 0; t < CHUNK; t++)
            wv[t] = *reinterpret_cast<const float4*>(w + (kk + t) * 128 + c0);
        #pragma unroll
        for (int t = 0; t < CHUNK; t++) {
            ull a[NP];
            #pragma unroll
            for (int p = 0; p < NP; p++)
                a[p] = lds64(in_t + (kk + t) * rs + r0 + 2 * p);
            const float wc[4] = {wv[t].x, wv[t].y, wv[t].z, wv[t].w};
            #pragma unroll
            for (int c = 0; c < 4; c++) {
                const ull b = pack2(wc[c], wc[c]);
                #pragma unroll
                for (int p = 0; p < NP; p++) ffma2(acc[c][p], a[p], b);
            }
        }
    }
}

template<int NP>
__device__ __forceinline__ void ffin(const ull (&acc)[4][NP], bool relu,
                                     float (&out)[4][2 * NP])
{
    #pragma unroll
    for (int c = 0; c < 4; c++)
        #pragma unroll
        for (int p = 0; p < NP; p++) {
            float lo, hi; unpack2(acc[c][p], lo, hi);
            if (relu) { lo = fmaxf(lo, 0.f); hi = fmaxf(hi, 0.f); }
            out[c][2 * p] = lo; out[c][2 * p + 1] = hi;
        }
}

// store [4 cols][2NP rows] into transposed smem [col][row] via STS.128
template<int NP>
__device__ __forceinline__ void store_t(float* buf, int rs, int c0, int r0,
                                        const float (&out)[4][2 * NP])
{
    #pragma unroll
    for (int c = 0; c < 4; c++)
        #pragma unroll
        for (int q = 0; q < NP / 2; q++)
            *reinterpret_cast<float4*>(buf + (c0 + c) * rs + r0 + 4 * q) =
                make_float4(out[c][4 * q], out[c][4 * q + 1],
                            out[c][4 * q + 2], out[c][4 * q + 3]);
}

// store to global [row][128] layout via STG.128 per row
template<int NP>
__device__ __forceinline__ void store_g(float* g, int row_base, int c0, int r0,
                                        const float (&out)[4][2 * NP])
{
    #pragma unroll
    for (int i = 0; i < 2 * NP; i++)
        *reinterpret_cast<float4*>(g + (row_base + r0 + i) * MID + c0) =
            make_float4(out[0][i], out[1][i], out[2][i], out[3][i]);
}

// ---------------------------------------------------------------------------
// KA: encoder (129 -> 128 relu -> 128) + u/v projections. 32 rows/block.
// lane -> cols 4*lane, warp -> rows 8*warp. smem 2 buffers (37KB).
// ---------------------------------------------------------------------------
__global__ __launch_bounds__(128)
void k_encode(const float* __restrict__ theta,
              const float* __restrict__ svec,
              const float* __restrict__ ivec,
              const float* __restrict__ w_in1, const float* __restrict__ b_in1,
              const float* __restrict__ w_in2, const float* __restrict__ b_in2,
              const float* __restrict__ w_e1,  const float* __restrict__ b_e1)
{
    __shared__ __align__(16) float bufA[129 * RS];   // xs, then n
    __shared__ __align__(16) float bufB[128 * RS];   // h

    const int j    = threadIdx.x;
    const int c0   = (j & 31) * 4;
    const int r0   = (j >> 5) * 8;
    const int base = blockIdx.x * TILE;

    for (int idx = j; idx < TILE * 129; idx += 128) {
        const int i = idx / 129, k = idx % 129;
        const int node = base + i;
        float val;
        if (k < 64)       val = theta[node * 64 + k];
        else if (k < 128) val = svec[node * 64 + (k - 64)];
        else              val = ivec[node];
        bufA[k * RS + i] = val;
    }
    __syncthreads();

    ull acc[4][4];
    float o[4][8];

    // in1: 129 -> 128, relu (K=128 in loop + manual tail k=128)
    finit<4>(acc, *reinterpret_cast<const float4*>(b_in1 + c0));
    fgemm<4, 4>(acc, bufA, RS, w_in1, 128, c0, r0);
    ffin<4>(acc, false, o);
    {
        const float4 wt = *reinterpret_cast<const float4*>(w_in1 + 128 * 128 + c0);
        const float wc[4] = {wt.x, wt.y, wt.z, wt.w};
        float a[8];
        #pragma unroll
        for (int i = 0; i < 8; i++) a[i] = bufA[128 * RS + r0 + i];
        #pragma unroll
        for (int c = 0; c < 4; c++)
            #pragma unroll
            for (int i = 0; i < 8; i++)
                o[c][i] = fmaxf(fmaf(a[i], wc[c], o[c][i]), 0.f);
    }
    store_t<4>(bufB, RS, c0, r0, o);
    __syncthreads();

    // in2: 128 -> 128 (no relu) -> n (bufA alias + global)
    finit<4>(acc, *reinterpret_cast<const float4*>(b_in2 + c0));
    fgemm<4, 4>(acc, bufB, RS, w_in2, 128, c0, r0);
    ffin<4>(acc, false, o);
    store_t<4>(bufA, RS, c0, r0, o);
    store_g<4>(g_n, base, c0, r0, o);
    __syncthreads();

    // u = n @ w_e1[0:128]
    finit<4>(acc, make_float4(0.f, 0.f, 0.f, 0.f));
    fgemm<4, 4>(acc, bufA, RS, w_e1, 128, c0, r0);
    ffin<4>(acc, false, o);
    store_g<4>(g_u, base, c0, r0, o);

    // v = n @ w_e1[128:256] + b_e1
    finit<4>(acc, *reinterpret_cast<const float4*>(b_e1 + c0));
    fgemm<4, 4>(acc, bufA, RS, w_e1 + 128 * 128, 128, c0, r0);
    ffin<4>(acc, false, o);
    store_g<4>(g_v, base, c0, r0, o);
}

// ---------------------------------------------------------------------------
// KB: one block per group (2048 blocks). e1 (45 rows, pad 48) transposed,
// e2 in ONE k-pass per half (NP=6: warp owns 12 rows), in-place overwrite,
// relu-sum per receiver (e3 linearity), e3 on 10 summed rows. Zero atomics.
// ---------------------------------------------------------------------------
__global__ __launch_bounds__(128)
void k_edge(const float* __restrict__ w_e2, const float* __restrict__ b_e2,
            const float* __restrict__ w_e3, const float* __restrict__ b_e3)
{
    __shared__ __align__(16) float u_s[10 * 128];
    __shared__ __align__(16) float v_s[10 * 128];
    __shared__ __align__(16) float e1t[128 * ERS];
    __shared__ __align__(16) float s2t[128 * 16];

    const int j     = threadIdx.x;
    const int c0    = (j & 31) * 4;
    const int r12   = (j >> 5) * 12;   // e2 row base (12 rows per warp)
    const int r4    = (j >> 5) * 4;    // e3 row base
    const int gbase = blockIdx.x * AA;

    #pragma unroll
    for (int a = 0; a < 10; a++) {
        u_s[a * 128 + j] = g_u[(gbase + a) * MID + j];
        v_s[a * 128 + j] = g_v[(gbase + a) * MID + j];
    }
    __syncthreads();

    const float4 be2 = *reinterpret_cast<const float4*>(b_e2 + c0);

    for (int half = 0; half < 2; half++) {
        // build e1 rows: row = r_loc*9 + ss, receiver r = half*5 + r_loc
        {
            float v[5];
            #pragma unroll
            for (int rl = 0; rl < 5; rl++) v[rl] = v_s[(half * 5 + rl) * 128 + j];
            #pragma unroll
            for (int m = 0; m < 12; m++) {
                float q[4];
                #pragma unroll
                for (int t = 0; t < 4; t++) {
                    const int row = 4 * m + t;
                    if (row < 45) {
                        const int rl = row / 9, ss = row % 9;
                        const int r  = half * 5 + rl;
                        const int s  = (ss < r) ? ss : ss + 1;
                        q[t] = fmaxf(u_s[s * 128 + j] + v[rl], 0.f);
                    } else q[t] = 0.f;
                }
                *reinterpret_cast<float4*>(e1t + j * ERS + 4 * m) =
                    make_float4(q[0], q[1], q[2], q[3]);
            }
        }
        __syncthreads();

        // e2: all 48 rows in ONE weight pass, relu, in-place (warp-disjoint)
        {
            ull acc6[4][6];
            finit<6>(acc6, be2);
            fgemm<6, 4>(acc6, e1t, ERS, w_e2, 128, c0, r12);
            float o12[4][12];
            ffin<6>(acc6, true, o12);
            store_t<6>(e1t, ERS, c0, r12, o12);
        }
        __syncthreads();

        // relu-sum over 9 senders per receiver -> s2t[k][recv]
        {
            const float* myrow = e1t + j * ERS;
            #pragma unroll
            for (int rl = 0; rl < 5; rl++) {
                float s = 0.f;
                #pragma unroll
                for (int ss = 0; ss < 9; ss++) s += myrow[rl * 9 + ss];
                s2t[j * 16 + half * 5 + rl] = s;
            }
            if (half == 0) {
                #pragma unroll
                for (int r = 10; r < 16; r++) s2t[j * 16 + r] = 0.f;
            }
        }
        __syncthreads();
    }

    // e3: 10 rows x 128 cols; agg = acc/9 + b_e3
    if (r4 < 10) {
        ull acc2[4][2];
        finit<2>(acc2, make_float4(0.f, 0.f, 0.f, 0.f));
        fgemm<2, 4>(acc2, s2t, 16, w_e3, 128, c0, r4);
        float o[4][4];
        ffin<2>(acc2, false, o);
        const float4 be3 = *reinterpret_cast<const float4*>(b_e3 + c0);
        const float bs[4] = {be3.x, be3.y, be3.z, be3.w};
        #pragma unroll
        for (int i = 0; i < 4; i++) {
            if (r4 + i < 10)
                *reinterpret_cast<float4*>(g_agg + (gbase + r4 + i) * MID + c0) =
                    make_float4(o[0][i] * (1.f / 9.f) + bs[0],
                                o[1][i] * (1.f / 9.f) + bs[1],
                                o[2][i] * (1.f / 9.f) + bs[2],
                                o[3][i] * (1.f / 9.f) + bs[3]);
        }
    }
}

// ---------------------------------------------------------------------------
// KC: node MLP (256 -> 128 relu -> 128 relu -> 128) + decoder (128 relu -> 8)
// 32 rows/block. n1's 256-wide input = two K=128 passes sharing one acc
// (g_n pass, then g_agg overwrites the same buffer). Two smem buffers.
// ---------------------------------------------------------------------------
__global__ __launch_bounds__(128)
void k_node(const float* __restrict__ w_n1, const float* __restrict__ b_n1,
            const float* __restrict__ w_n2, const float* __restrict__ b_n2,
            const float* __restrict__ w_n3, const float* __restrict__ b_n3,
            const float* __restrict__ w_l1, const float* __restrict__ b_l1,
            const float* __restrict__ w_l2, const float* __restrict__ b_l2,
            float* __restrict__ out)
{
    __shared__ __align__(16) float bufA[128 * RS];
    __shared__ __align__(16) float bufB[128 * RS];

    const int j    = threadIdx.x;
    const int c0   = (j & 31) * 4;
    const int r0   = (j >> 5) * 8;
    const int base = blockIdx.x * TILE;

    // load g_n part
    for (int idx = j; idx < TILE * 128; idx += 128) {
        const int i = idx >> 7, k = idx & 127;
        bufA[k * RS + i] = g_n[(base + i) * MID + k];
    }
    __syncthreads();

    ull acc[4][4];
    float o[4][8];

    // n1 part 1: over g_n with w_n1[0:128]
    finit<4>(acc, *reinterpret_cast<const float4*>(b_n1 + c0));
    fgemm<4, 4>(acc, bufA, RS, w_n1, 128, c0, r0);
    __syncthreads();                       // all reads of bufA done

    // swap in g_agg, accumulate with w_n1[128:256]
    for (int idx = j; idx < TILE * 128; idx += 128) {
        const int i = idx >> 7, k = idx & 127;
        bufA[k * RS + i] = g_agg[(base + i) * MID + k];
    }
    __syncthreads();
    fgemm<4, 4>(acc, bufA, RS, w_n1 + 128 * 128, 128, c0, r0);
    ffin<4>(acc, true, o);
    store_t<4>(bufB, RS, c0, r0, o);
    __syncthreads();

    // n2: bufB -> bufA, relu
    finit<4>(acc, *reinterpret_cast<const float4*>(b_n2 + c0));
    fgemm<4, 4>(acc, bufB, RS, w_n2, 128, c0, r0);
    ffin<4>(acc, true, o);
    store_t<4>(bufA, RS, c0, r0, o);
    __syncthreads();

    // n3: bufA -> bufB, no relu
    finit<4>(acc, *reinterpret_cast<const float4*>(b_n3 + c0));
    fgemm<4, 4>(acc, bufA, RS, w_n3, 128, c0, r0);
    ffin<4>(acc, false, o);
    store_t<4>(bufB, RS, c0, r0, o);
    __syncthreads();

    // l1: bufB -> bufA, relu
    finit<4>(acc, *reinterpret_cast<const float4*>(b_l1 + c0));
    fgemm<4, 4>(acc, bufB, RS, w_l1, 128, c0, r0);
    ffin<4>(acc, true, o);
    store_t<4>(bufA, RS, c0, r0, o);
    __syncthreads();

    // l2: 128 -> 8. 256 outputs, 128 threads -> 2 each
    {
        const int c = j & 7;
        #pragma unroll
        for (int rr = 0; rr < 2; rr++) {
            const int i = (j >> 3) + rr * 16;
            float s = b_l2[c];
            #pragma unroll 8
            for (int k = 0; k < 128; k++)
                s = fmaf(bufA[k * RS + i], w_l2[k * ACT + c], s);
            out[(base + i) * ACT + c] = s;
        }
    }
}

// ---------------------------------------------------------------------------
// Host-side input resolution by SIZE CLASS (== dict mapping, proven R7).
// ---------------------------------------------------------------------------
extern "C" void kernel_launch(void* const* d_in, const int* in_sizes, int n_in,
                              void* d_out, int out_size)
{
    int scale = 1;
    {
        bool elems = false, bytes = false;
        for (int t = 0; t < n_in; t++) {
            if (in_sizes[t] == 16512) elems = true;
            if (in_sizes[t] == 66048) bytes = true;
        }
        if (!elems && bytes) scale = 4;
    }

    int posBig[2] = {-1, -1}; int nBig = 0;
    int posW32[2] = {-1, -1}; int nW32 = 0;
    int posW16[6] = {-1, -1, -1, -1, -1, -1}; int nW16 = 0;
    int posB[9]   = {-1, -1, -1, -1, -1, -1, -1, -1, -1}; int nB = 0;
    int pI = -1, pWin1 = -1, pWl2 = -1, pBl2 = -1;

    for (int t = 0; t < n_in; t++) {
        const int sz = in_sizes[t] / scale;
        if      (sz == 1310720) { if (nBig < 2) posBig[nBig++] = t; }
        else if (sz == 32768)   { if (nW32 < 2) posW32[nW32++] = t; }
        else if (sz == 16384)   { if (nW16 < 6) posW16[nW16++] = t; }
        else if (sz == 128)     { if (nB   < 9) posB[nB++]     = t; }
        else if (sz == 20480)   { pI    = t; }
        else if (sz == 16512)   { pWin1 = t; }
        else if (sz == 1024)    { pWl2  = t; }
        else if (sz == 8)       { pBl2  = t; }
    }

    if (nBig < 2 || nW32 < 2 || nW16 < 6 || nB < 9 ||
        pI < 0 || pWin1 < 0 || pWl2 < 0 || pBl2 < 0) {
        posBig[0] = 0;  posBig[1] = 1;  pI = 2;
        pWin1 = 5;
        posB[0] = 6;    posW16[0] = 7;  posB[1] = 8;
        posW32[0] = 9;  posB[2] = 10;
        posW16[1] = 11; posB[3] = 12;
        posW16[2] = 13; posB[4] = 14;
        posW32[1] = 15; posB[5] = 16;
        posW16[3] = 17; posB[6] = 18;
        posW16[4] = 19; posB[7] = 20;
        posW16[5] = 21; posB[8] = 22;
        pWl2 = 23; pBl2 = 24;
    }

    const float* theta = (const float*)d_in[posBig[0]];
    const float* svec  = (const float*)d_in[posBig[1]];
    const float* ivec  = (const float*)d_in[pI];
    const float* w_in1 = (const float*)d_in[pWin1];
    const float* w_in2 = (const float*)d_in[posW16[0]];
    const float* w_e1  = (const float*)d_in[posW32[0]];
    const float* w_e2  = (const float*)d_in[posW16[1]];
    const float* w_e3  = (const float*)d_in[posW16[2]];
    const float* w_n1  = (const float*)d_in[posW32[1]];
    const float* w_n2  = (const float*)d_in[posW16[3]];
    const float* w_n3  = (const float*)d_in[posW16[4]];
    const float* w_l1  = (const float*)d_in[posW16[5]];
    const float* w_l2  = (const float*)d_in[pWl2];
    const float* b_in1 = (const float*)d_in[posB[0]];
    const float* b_in2 = (const float*)d_in[posB[1]];
    const float* b_e1  = (const float*)d_in[posB[2]];
    const float* b_e2  = (const float*)d_in[posB[3]];
    const float* b_e3  = (const float*)d_in[posB[4]];
    const float* b_n1  = (const float*)d_in[posB[5]];
    const float* b_n2  = (const float*)d_in[posB[6]];
    const float* b_n3  = (const float*)d_in[posB[7]];
    const float* b_l1  = (const float*)d_in[posB[8]];
    const float* b_l2  = (const float*)d_in[pBl2];
    float* out = (float*)d_out;

    k_encode<<<NN / TILE, 128>>>(theta, svec, ivec,
                                 w_in1, b_in1, w_in2, b_in2, w_e1, b_e1);
    k_edge<<<NN / AA, 128>>>(w_e2, b_e2, w_e3, b_e3);
    k_node<<<NN / TILE, 128>>>(w_n1, b_n1, w_n2, b_n2, w_n3, b_n3,
                               w_l1, b_l1, w_l2, b_l2, out);
}

// round 17
// speedup vs baseline: 1.0023x; 1.0007x over previous
#include <cuda_runtime.h>
#include <cuda_bf16.h>

// Problem constants (fixed by the reference)
#define NN    20480      // B*P*A total nodes
#define AA    10         // agents per group
#define MID   128
#define TILE  32         // rows per block in encode/node kernels
#define ACT   8
#define RS    36         // transposed smem row stride (floats) for encode/node
#define ERS   52         // e1t row stride in k_edge

typedef unsigned long long ull;

// Scratch (device globals — no allocation allowed)
__device__ float g_n[NN * MID];
__device__ float g_u[NN * MID];
__device__ float g_v[NN * MID];     // includes b_e1 folded in
__device__ float g_agg[NN * MID];

// ---- packed f32x2 helpers ---------------------------------------------------
__device__ __forceinline__ ull pack2(float lo, float hi) {
    ull r; asm("mov.b64 %0, {%1, %2};" : "=l"(r) : "f"(lo), "f"(hi)); return r;
}
__device__ __forceinline__ void unpack2(ull v, float& lo, float& hi) {
    asm("mov.b64 {%0, %1}, %2;" : "=f"(lo), "=f"(hi) : "l"(v));
}
__device__ __forceinline__ void ffma2(ull& d, ull a, ull b) {
    asm("fma.rn.f32x2 %0, %1, %2, %0;" : "+l"(d) : "l"(a), "l"(b));
}
__device__ __forceinline__ ull lds64(const float* p) {
    return *reinterpret_cast<const ull*>(p);
}

// ---------------------------------------------------------------------------
// Generalized register-tiled GEMM fragment: 4 cols x NP row-pairs per thread.
//  acc[c][p] accumulates cols c0+c, rows (r0+2p, r0+2p+1).
//  Weights front-batched CHUNK at a time (CHUNK LDG.128 in flight).
// ---------------------------------------------------------------------------
template<int NP>
__device__ __forceinline__ void finit(ull (&acc)[4][NP], float4 b) {
    const float bc[4] = {b.x, b.y, b.z, b.w};
    #pragma unroll
    for (int c = 0; c < 4; c++) {
        const ull bb = pack2(bc[c], bc[c]);
        #pragma unroll
        for (int p = 0; p < NP; p++) acc[c][p] = bb;
    }
}

template<int NP, int CHUNK>
__device__ __forceinline__ void fgemm(ull (&acc)[4][NP],
                                      const float* __restrict__ in_t, int rs,
                                      const float* __restrict__ w,
                                      int K, int c0, int r0)
{
    for (int kk = 0; kk < K; kk += CHUNK) {
        float4 wv[CHUNK];
        #pragma unroll
        for (int t = 0; t < CHUNK; t++)
            wv[t] = *reinterpret_cast<const float4*>(w + (kk + t) * 128 + c0);
        #pragma unroll
        for (int t = 0; t < CHUNK; t++) {
            ull a[NP];
            #pragma unroll
            for (int p = 0; p < NP; p++)
                a[p] = lds64(in_t + (kk + t) * rs + r0 + 2 * p);
            const float wc[4] = {wv[t].x, wv[t].y, wv[t].z, wv[t].w};
            #pragma unroll
            for (int c = 0; c < 4; c++) {
                const ull b = pack2(wc[c], wc[c]);
                #pragma unroll
                for (int p = 0; p < NP; p++) ffma2(acc[c][p], a[p], b);
            }
        }
    }
}

template<int NP>
__device__ __forceinline__ void ffin(const ull (&acc)[4][NP], bool relu,
                                     float (&out)[4][2 * NP])
{
    #pragma unroll
    for (int c = 0; c < 4; c++)
        #pragma unroll
        for (int p = 0; p < NP; p++) {
            float lo, hi; unpack2(acc[c][p], lo, hi);
            if (relu) { lo = fmaxf(lo, 0.f); hi = fmaxf(hi, 0.f); }
            out[c][2 * p] = lo; out[c][2 * p + 1] = hi;
        }
}

// store [4 cols][2NP rows] into transposed smem [col][row] via STS.128
template<int NP>
__device__ __forceinline__ void store_t(float* buf, int rs, int c0, int r0,
                                        const float (&out)[4][2 * NP])
{
    #pragma unroll
    for (int c = 0; c < 4; c++)
        #pragma unroll
        for (int q = 0; q < NP / 2; q++)
            *reinterpret_cast<float4*>(buf + (c0 + c) * rs + r0 + 4 * q) =
                make_float4(out[c][4 * q], out[c][4 * q + 1],
                            out[c][4 * q + 2], out[c][4 * q + 3]);
}

// store to global [row][128] layout via STG.128 per row
template<int NP>
__device__ __forceinline__ void store_g(float* g, int row_base, int c0, int r0,
                                        const float (&out)[4][2 * NP])
{
    #pragma unroll
    for (int i = 0; i < 2 * NP; i++)
        *reinterpret_cast<float4*>(g + (row_base + r0 + i) * MID + c0) =
            make_float4(out[0][i], out[1][i], out[2][i], out[3][i]);
}

// ---------------------------------------------------------------------------
// KA: encoder (129 -> 128 relu -> 128) + u/v projections. 32 rows/block.
// lane -> cols 4*lane, warp -> rows 8*warp. smem 2 buffers (37KB).
// ---------------------------------------------------------------------------
__global__ __launch_bounds__(128)
void k_encode(const float* __restrict__ theta,
              const float* __restrict__ svec,
              const float* __restrict__ ivec,
              const float* __restrict__ w_in1, const float* __restrict__ b_in1,
              const float* __restrict__ w_in2, const float* __restrict__ b_in2,
              const float* __restrict__ w_e1,  const float* __restrict__ b_e1)
{
    __shared__ __align__(16) float bufA[129 * RS];   // xs, then n
    __shared__ __align__(16) float bufB[128 * RS];   // h

    const int j    = threadIdx.x;
    const int c0   = (j & 31) * 4;
    const int r0   = (j >> 5) * 8;
    const int base = blockIdx.x * TILE;

    for (int idx = j; idx < TILE * 129; idx += 128) {
        const int i = idx / 129, k = idx % 129;
        const int node = base + i;
        float val;
        if (k < 64)       val = theta[node * 64 + k];
        else if (k < 128) val = svec[node * 64 + (k - 64)];
        else              val = ivec[node];
        bufA[k * RS + i] = val;
    }
    __syncthreads();

    ull acc[4][4];
    float o[4][8];

    // in1: 129 -> 128, relu (K=128 in loop + manual tail k=128)
    finit<4>(acc, *reinterpret_cast<const float4*>(b_in1 + c0));
    fgemm<4, 4>(acc, bufA, RS, w_in1, 128, c0, r0);
    ffin<4>(acc, false, o);
    {
        const float4 wt = *reinterpret_cast<const float4*>(w_in1 + 128 * 128 + c0);
        const float wc[4] = {wt.x, wt.y, wt.z, wt.w};
        float a[8];
        #pragma unroll
        for (int i = 0; i < 8; i++) a[i] = bufA[128 * RS + r0 + i];
        #pragma unroll
        for (int c = 0; c < 4; c++)
            #pragma unroll
            for (int i = 0; i < 8; i++)
                o[c][i] = fmaxf(fmaf(a[i], wc[c], o[c][i]), 0.f);
    }
    store_t<4>(bufB, RS, c0, r0, o);
    __syncthreads();

    // in2: 128 -> 128 (no relu) -> n (bufA alias + global)
    finit<4>(acc, *reinterpret_cast<const float4*>(b_in2 + c0));
    fgemm<4, 4>(acc, bufB, RS, w_in2, 128, c0, r0);
    ffin<4>(acc, false, o);
    store_t<4>(bufA, RS, c0, r0, o);
    store_g<4>(g_n, base, c0, r0, o);
    __syncthreads();

    // u = n @ w_e1[0:128]
    finit<4>(acc, make_float4(0.f, 0.f, 0.f, 0.f));
    fgemm<4, 4>(acc, bufA, RS, w_e1, 128, c0, r0);
    ffin<4>(acc, false, o);
    store_g<4>(g_u, base, c0, r0, o);

    // v = n @ w_e1[128:256] + b_e1
    finit<4>(acc, *reinterpret_cast<const float4*>(b_e1 + c0));
    fgemm<4, 4>(acc, bufA, RS, w_e1 + 128 * 128, 128, c0, r0);
    ffin<4>(acc, false, o);
    store_g<4>(g_v, base, c0, r0, o);
}

// ---------------------------------------------------------------------------
// KB: one block per group (2048 blocks). e1 (45 rows, pad 48) transposed,
// e2 in ONE k-pass per half (NP=6: warp owns 12 rows), in-place overwrite,
// relu-sum per receiver (e3 linearity), e3 on 10 summed rows. Zero atomics.
// ---------------------------------------------------------------------------
__global__ __launch_bounds__(128)
void k_edge(const float* __restrict__ w_e2, const float* __restrict__ b_e2,
            const float* __restrict__ w_e3, const float* __restrict__ b_e3)
{
    __shared__ __align__(16) float u_s[10 * 128];
    __shared__ __align__(16) float v_s[10 * 128];
    __shared__ __align__(16) float e1t[128 * ERS];
    __shared__ __align__(16) float s2t[128 * 16];

    const int j     = threadIdx.x;
    const int c0    = (j & 31) * 4;
    const int r12   = (j >> 5) * 12;   // e2 row base (12 rows per warp)
    const int r4    = (j >> 5) * 4;    // e3 row base
    const int gbase = blockIdx.x * AA;

    #pragma unroll
    for (int a = 0; a < 10; a++) {
        u_s[a * 128 + j] = g_u[(gbase + a) * MID + j];
        v_s[a * 128 + j] = g_v[(gbase + a) * MID + j];
    }
    __syncthreads();

    const float4 be2 = *reinterpret_cast<const float4*>(b_e2 + c0);

    for (int half = 0; half < 2; half++) {
        // build e1 rows: row = r_loc*9 + ss, receiver r = half*5 + r_loc
        {
            float v[5];
            #pragma unroll
            for (int rl = 0; rl < 5; rl++) v[rl] = v_s[(half * 5 + rl) * 128 + j];
            #pragma unroll
            for (int m = 0; m < 12; m++) {
                float q[4];
                #pragma unroll
                for (int t = 0; t < 4; t++) {
                    const int row = 4 * m + t;
                    if (row < 45) {
                        const int rl = row / 9, ss = row % 9;
                        const int r  = half * 5 + rl;
                        const int s  = (ss < r) ? ss : ss + 1;
                        q[t] = fmaxf(u_s[s * 128 + j] + v[rl], 0.f);
                    } else q[t] = 0.f;
                }
                *reinterpret_cast<float4*>(e1t + j * ERS + 4 * m) =
                    make_float4(q[0], q[1], q[2], q[3]);
            }
        }
        __syncthreads();

        // e2: all 48 rows in ONE weight pass, relu, in-place (warp-disjoint)
        {
            ull acc6[4][6];
            finit<6>(acc6, be2);
            fgemm<6, 4>(acc6, e1t, ERS, w_e2, 128, c0, r12);
            float o12[4][12];
            ffin<6>(acc6, true, o12);
            store_t<6>(e1t, ERS, c0, r12, o12);
        }
        __syncthreads();

        // relu-sum over 9 senders per receiver -> s2t[k][recv]
        {
            const float* myrow = e1t + j * ERS;
            #pragma unroll
            for (int rl = 0; rl < 5; rl++) {
                float s = 0.f;
                #pragma unroll
                for (int ss = 0; ss < 9; ss++) s += myrow[rl * 9 + ss];
                s2t[j * 16 + half * 5 + rl] = s;
            }
            if (half == 0) {
                #pragma unroll
                for (int r = 10; r < 16; r++) s2t[j * 16 + r] = 0.f;
            }
        }
        __syncthreads();
    }

    // e3: 10 rows x 128 cols; agg = acc/9 + b_e3
    if (r4 < 10) {
        ull acc2[4][2];
        finit<2>(acc2, make_float4(0.f, 0.f, 0.f, 0.f));
        fgemm<2, 4>(acc2, s2t, 16, w_e3, 128, c0, r4);
        float o[4][4];
        ffin<2>(acc2, false, o);
        const float4 be3 = *reinterpret_cast<const float4*>(b_e3 + c0);
        const float bs[4] = {be3.x, be3.y, be3.z, be3.w};
        #pragma unroll
        for (int i = 0; i < 4; i++) {
            if (r4 + i < 10)
                *reinterpret_cast<float4*>(g_agg + (gbase + r4 + i) * MID + c0) =
                    make_float4(o[0][i] * (1.f / 9.f) + bs[0],
                                o[1][i] * (1.f / 9.f) + bs[1],
                                o[2][i] * (1.f / 9.f) + bs[2],
                                o[3][i] * (1.f / 9.f) + bs[3]);
        }
    }
}

// ---------------------------------------------------------------------------
// KC: node MLP (256 -> 128 relu -> 128 relu -> 128) + decoder (128 relu -> 8)
// 32 rows/block. n1's 256-wide input = two K=128 passes sharing one acc
// (g_n pass, then g_agg overwrites the same buffer). Two smem buffers.
// ---------------------------------------------------------------------------
__global__ __launch_bounds__(128)
void k_node(const float* __restrict__ w_n1, const float* __restrict__ b_n1,
            const float* __restrict__ w_n2, const float* __restrict__ b_n2,
            const float* __restrict__ w_n3, const float* __restrict__ b_n3,
            const float* __restrict__ w_l1, const float* __restrict__ b_l1,
            const float* __restrict__ w_l2, const float* __restrict__ b_l2,
            float* __restrict__ out)
{
    __shared__ __align__(16) float bufA[128 * RS];
    __shared__ __align__(16) float bufB[128 * RS];

    const int j    = threadIdx.x;
    const int c0   = (j & 31) * 4;
    const int r0   = (j >> 5) * 8;
    const int base = blockIdx.x * TILE;

    // load g_n part
    for (int idx = j; idx < TILE * 128; idx += 128) {
        const int i = idx >> 7, k = idx & 127;
        bufA[k * RS + i] = g_n[(base + i) * MID + k];
    }
    __syncthreads();

    ull acc[4][4];
    float o[4][8];

    // n1 part 1: over g_n with w_n1[0:128]
    finit<4>(acc, *reinterpret_cast<const float4*>(b_n1 + c0));
    fgemm<4, 4>(acc, bufA, RS, w_n1, 128, c0, r0);
    __syncthreads();                       // all reads of bufA done

    // swap in g_agg, accumulate with w_n1[128:256]
    for (int idx = j; idx < TILE * 128; idx += 128) {
        const int i = idx >> 7, k = idx & 127;
        bufA[k * RS + i] = g_agg[(base + i) * MID + k];
    }
    __syncthreads();
    fgemm<4, 4>(acc, bufA, RS, w_n1 + 128 * 128, 128, c0, r0);
    ffin<4>(acc, true, o);
    store_t<4>(bufB, RS, c0, r0, o);
    __syncthreads();

    // n2: bufB -> bufA, relu
    finit<4>(acc, *reinterpret_cast<const float4*>(b_n2 + c0));
    fgemm<4, 4>(acc, bufB, RS, w_n2, 128, c0, r0);
    ffin<4>(acc, true, o);
    store_t<4>(bufA, RS, c0, r0, o);
    __syncthreads();

    // n3: bufA -> bufB, no relu
    finit<4>(acc, *reinterpret_cast<const float4*>(b_n3 + c0));
    fgemm<4, 4>(acc, bufA, RS, w_n3, 128, c0, r0);
    ffin<4>(acc, false, o);
    store_t<4>(bufB, RS, c0, r0, o);
    __syncthreads();

    // l1: bufB -> bufA, relu
    finit<4>(acc, *reinterpret_cast<const float4*>(b_l1 + c0));
    fgemm<4, 4>(acc, bufB, RS, w_l1, 128, c0, r0);
    ffin<4>(acc, true, o);
    store_t<4>(bufA, RS, c0, r0, o);
    __syncthreads();

    // l2: 128 -> 8. 256 outputs, 128 threads -> 2 each
    {
        const int c = j & 7;
        #pragma unroll
        for (int rr = 0; rr < 2; rr++) {
            const int i = (j >> 3) + rr * 16;
            float s = b_l2[c];
            #pragma unroll 8
            for (int k = 0; k < 128; k++)
                s = fmaf(bufA[k * RS + i], w_l2[k * ACT + c], s);
            out[(base + i) * ACT + c] = s;
        }
    }
}

// ---------------------------------------------------------------------------
// Host-side input resolution by SIZE CLASS (== dict mapping, proven R7).
// ---------------------------------------------------------------------------
extern "C" void kernel_launch(void* const* d_in, const int* in_sizes, int n_in,
                              void* d_out, int out_size)
{
    int scale = 1;
    {
        bool elems = false, bytes = false;
        for (int t = 0; t < n_in; t++) {
            if (in_sizes[t] == 16512) elems = true;
            if (in_sizes[t] == 66048) bytes = true;
        }
        if (!elems && bytes) scale = 4;
    }

    int posBig[2] = {-1, -1}; int nBig = 0;
    int posW32[2] = {-1, -1}; int nW32 = 0;
    int posW16[6] = {-1, -1, -1, -1, -1, -1}; int nW16 = 0;
    int posB[9]   = {-1, -1, -1, -1, -1, -1, -1, -1, -1}; int nB = 0;
    int pI = -1, pWin1 = -1, pWl2 = -1, pBl2 = -1;

    for (int t = 0; t < n_in; t++) {
        const int sz = in_sizes[t] / scale;
        if      (sz == 1310720) { if (nBig < 2) posBig[nBig++] = t; }
        else if (sz == 32768)   { if (nW32 < 2) posW32[nW32++] = t; }
        else if (sz == 16384)   { if (nW16 < 6) posW16[nW16++] = t; }
        else if (sz == 128)     { if (nB   < 9) posB[nB++]     = t; }
        else if (sz == 20480)   { pI    = t; }
        else if (sz == 16512)   { pWin1 = t; }
        else if (sz == 1024)    { pWl2  = t; }
        else if (sz == 8)       { pBl2  = t; }
    }

    if (nBig < 2 || nW32 < 2 || nW16 < 6 || nB < 9 ||
        pI < 0 || pWin1 < 0 || pWl2 < 0 || pBl2 < 0) {
        posBig[0] = 0;  posBig[1] = 1;  pI = 2;
        pWin1 = 5;
        posB[0] = 6;    posW16[0] = 7;  posB[1] = 8;
        posW32[0] = 9;  posB[2] = 10;
        posW16[1] = 11; posB[3] = 12;
        posW16[2] = 13; posB[4] = 14;
        posW32[1] = 15; posB[5] = 16;
        posW16[3] = 17; posB[6] = 18;
        posW16[4] = 19; posB[7] = 20;
        posW16[5] = 21; posB[8] = 22;
        pWl2 = 23; pBl2 = 24;
    }

    const float* theta = (const float*)d_in[posBig[0]];
    const float* svec  = (const float*)d_in[posBig[1]];
    const float* ivec  = (const float*)d_in[pI];
    const float* w_in1 = (const float*)d_in[pWin1];
    const float* w_in2 = (const float*)d_in[posW16[0]];
    const float* w_e1  = (const float*)d_in[posW32[0]];
    const float* w_e2  = (const float*)d_in[posW16[1]];
    const float* w_e3  = (const float*)d_in[posW16[2]];
    const float* w_n1  = (const float*)d_in[posW32[1]];
    const float* w_n2  = (const float*)d_in[posW16[3]];
    const float* w_n3  = (const float*)d_in[posW16[4]];
    const float* w_l1  = (const float*)d_in[posW16[5]];
    const float* w_l2  = (const float*)d_in[pWl2];
    const float* b_in1 = (const float*)d_in[posB[0]];
    const float* b_in2 = (const float*)d_in[posB[1]];
    const float* b_e1  = (const float*)d_in[posB[2]];
    const float* b_e2  = (const float*)d_in[posB[3]];
    const float* b_e3  = (const float*)d_in[posB[4]];
    const float* b_n1  = (const float*)d_in[posB[5]];
    const float* b_n2  = (const float*)d_in[posB[6]];
    const float* b_n3  = (const float*)d_in[posB[7]];
    const float* b_l1  = (const float*)d_in[posB[8]];
    const float* b_l2  = (const float*)d_in[pBl2];
    float* out = (float*)d_out;

    k_encode<<<NN / TILE, 128>>>(theta, svec, ivec,
                                 w_in1, b_in1, w_in2, b_in2, w_e1, b_e1);
    k_edge<<<NN / AA, 128>>>(w_e2, b_e2, w_e3, b_e3);
    k_node<<<NN / TILE, 128>>>(w_n1, b_n1, w_n2, b_n2, w_n3, b_n3,
                               w_l1, b_l1, w_l2, b_l2, out);
}